// round 8
// baseline (speedup 1.0000x reference)
#include <cuda_runtime.h>
#include <cuda_bf16.h>
#include <cstdint>

#define NB 32
#define NM 2048
#define ND 1024
#define NK 64
#define BM (NB*NM)   // 65536 rows total

// ---------------- scratch (device globals; no allocs allowed) ----------------
__device__ __nv_bfloat16 g_x16[(size_t)BM * ND];       // 128 MB bf16(x) RAW (not normalized)
__device__ __nv_bfloat16 g_w16[NK * ND];               // W in bf16, k-PERMUTED within 16-groups
__device__ __nv_bfloat16 g_a[(size_t)BM * NK];         // p[m,k] * inv_m  (bf16)
__device__ float         g_asum[NB * NK];              // sum_m p[b,m,k]  (unscaled)
__device__ float         g_vfin[(size_t)NB * NK * ND]; // centroid-subtracted vlad (unscaled)
__device__ float         g_ssq[NB * NK * 8];           // per-(b,k) sumsq partials, 8 d-tiles

// ---------------- helpers ----------------
static __device__ __forceinline__ unsigned s2u(const void* p) {
    return (unsigned)__cvta_generic_to_shared(p);
}
static __device__ __forceinline__ void cp16(unsigned dst, const void* src) {
    asm volatile("cp.async.cg.shared.global [%0], [%1], 16;\n" :: "r"(dst), "l"(src));
}
static __device__ __forceinline__ void cp_commit() {
    asm volatile("cp.async.commit_group;\n");
}
template<int N> static __device__ __forceinline__ void cp_wait() {
    asm volatile("cp.async.wait_group %0;\n" :: "n"(N));
}
static __device__ __forceinline__ void ldsm_x4(unsigned& r0, unsigned& r1, unsigned& r2, unsigned& r3, unsigned a) {
    asm volatile("ldmatrix.sync.aligned.m8n8.x4.shared.b16 {%0,%1,%2,%3}, [%4];"
                 : "=r"(r0), "=r"(r1), "=r"(r2), "=r"(r3) : "r"(a));
}
static __device__ __forceinline__ void ldsm_x4t(unsigned& r0, unsigned& r1, unsigned& r2, unsigned& r3, unsigned a) {
    asm volatile("ldmatrix.sync.aligned.m8n8.x4.trans.shared.b16 {%0,%1,%2,%3}, [%4];"
                 : "=r"(r0), "=r"(r1), "=r"(r2), "=r"(r3) : "r"(a));
}
static __device__ __forceinline__ void mma16816(float* c,
        unsigned a0, unsigned a1, unsigned a2, unsigned a3, unsigned b0, unsigned b1) {
    asm volatile("mma.sync.aligned.m16n8k16.row.col.f32.bf16.bf16.f32 "
                 "{%0,%1,%2,%3}, {%4,%5,%6,%7}, {%8,%9}, {%0,%1,%2,%3};"
                 : "+f"(c[0]), "+f"(c[1]), "+f"(c[2]), "+f"(c[3])
                 : "r"(a0), "r"(a1), "r"(a2), "r"(a3), "r"(b0), "r"(b1));
}
static __device__ __forceinline__ unsigned packbf(float a, float b) {
    __nv_bfloat162 h;
    h.x = __float2bfloat16_rn(a);
    h.y = __float2bfloat16_rn(b);
    return *reinterpret_cast<unsigned*>(&h);
}

// ---------------- kernel 0: W -> bf16 (k-permuted), zero a_sum ----------------
// Permutation within each 16-col group: logical j -> slot 2*(j>>2)+(j&1)+((j&2)?8:0),
// matching A-fragments built straight from float4 LDGs.
__global__ __launch_bounds__(256) void k_wconv(const float* __restrict__ W) {
    int i = blockIdx.x * 256 + threadIdx.x;       // grid 256 -> exactly NK*ND
    int kl = i & (ND - 1);
    int j  = kl & 15;
    int sl = 2 * (j >> 2) + (j & 1) + ((j & 2) ? 8 : 0);
    int oc = (kl & ~15) | sl;
    g_w16[(i & ~(ND - 1)) | oc] = __float2bfloat16_rn(W[i]);
    if (i < NB * NK) g_asum[i] = 0.f;
}

// ============ fused: x->bf16 + logits GEMM + row-norm + softmax + a_sum ============
// 128 rows per block (grid 512), 1 CTA/SM. W is FULLY RESIDENT in smem (loaded
// once); the main loop has NO barriers / cp.async — warps free-run on scoreboards:
// LDG x fp32 -> cvt (A-fragments in regs) -> STG raw bf16 -> LDSM W -> MMA.
//
// dyn smem layout (bytes):
//   ws    [64][1032] bf16 @ 0       132096
//   lg    [128][66]  f32  @ 132096   33792
//   ssrow [128]      f32  @ 165888     512
//   sas   [64]       f32  @ 166400     256
#define NL_SMEM 166656
__global__ __launch_bounds__(256, 1) void k_nl(const float* __restrict__ x) {
    extern __shared__ __align__(16) unsigned char dsm[];
    __nv_bfloat16* ws = (__nv_bfloat16*)dsm;
    float* lg    = (float*)(dsm + 132096);
    float* ssrow = (float*)(dsm + 165888);
    float* sas   = (float*)(dsm + 166400);

    const int tid = threadIdx.x, lane = tid & 31, warp = tid >> 5;
    const int m0 = blockIdx.x * 128;
    const int b  = m0 >> 11;

    if (tid < 64) sas[tid] = 0.f;

    // ---- load W once: 64 rows x 1024 bf16 (2048 B/row), 32 cp16 per thread ----
#pragma unroll
    for (int it = 0; it < 32; it++) {
        int idx = tid + it * 256;
        int r = idx >> 7, c = idx & 127;            // 128 x 16B per row
        cp16(s2u(ws + r * 1032 + c * 8), g_w16 + (size_t)r * ND + c * 8);
    }
    cp_commit();

    const int gr = lane >> 2, q = lane & 3;
    const int ar = warp * 16;                       // warp's 16 m-rows
    const size_t row0 = (size_t)(m0 + ar + gr);     // lo row; hi row = row0 + 8
    const float* xb = x + row0 * ND + q * 4;

    float4 xr[2][4][2];
    float ss0 = 0.f, ss1 = 0.f;

    float acc[8][4];
#pragma unroll
    for (int i = 0; i < 8; i++)
#pragma unroll
        for (int j = 0; j < 4; j++) acc[i][j] = 0.f;

    // ---- prologue: prefetch chunks 0,1 into regs; wait W; single barrier ----
#pragma unroll
    for (int ds = 0; ds < 4; ds++) {
        xr[0][ds][0] = *(const float4*)(xb + ds * 16);
        xr[0][ds][1] = *(const float4*)(xb + ds * 16 + 8 * ND);
        xr[1][ds][0] = *(const float4*)(xb + 64 + ds * 16);
        xr[1][ds][1] = *(const float4*)(xb + 64 + ds * 16 + 8 * ND);
    }
    cp_wait<0>();
    __syncthreads();                                // ws visible to all; last sync until epilogue

    // ---- main loop: free-running, no synchronization ----
    auto body = [&](int ch, int cb) {
#pragma unroll
        for (int ds = 0; ds < 4; ds++) {
            float4 f0 = xr[cb][ds][0];
            float4 f1 = xr[cb][ds][1];
            ss0 += f0.x * f0.x + f0.y * f0.y + f0.z * f0.z + f0.w * f0.w;
            ss1 += f1.x * f1.x + f1.y * f1.y + f1.z * f1.z + f1.w * f1.w;
            unsigned a0 = packbf(f0.x, f0.y), a2 = packbf(f0.z, f0.w);
            unsigned a1 = packbf(f1.x, f1.y), a3 = packbf(f1.z, f1.w);
            {   // raw bf16 out (natural order) for k_vlad
                __nv_bfloat16* gx = g_x16 + row0 * ND + ch * 64 + ds * 16 + q * 4;
                uint2 u0; u0.x = a0; u0.y = a2;
                uint2 u1; u1.x = a1; u1.y = a3;
                *(uint2*)gx            = u0;
                *(uint2*)(gx + 8 * ND) = u1;
            }
#pragma unroll
            for (int nt = 0; nt < 8; nt += 2) {
                unsigned b0, b1, b2, b3;
                int r = nt * 8 + (lane & 7) + ((lane >> 4) & 1) * 8;
                int c = ch * 64 + ds * 16 + ((lane >> 3) & 1) * 8;
                ldsm_x4(b0, b1, b2, b3, s2u(ws + r * 1032 + c));
                mma16816(acc[nt],     a0, a1, a2, a3, b0, b1);
                mma16816(acc[nt + 1], a0, a1, a2, a3, b2, b3);
            }
        }
        if (ch + 2 < 16) {
#pragma unroll
            for (int ds = 0; ds < 4; ds++) {
                xr[cb][ds][0] = *(const float4*)(xb + (ch + 2) * 64 + ds * 16);
                xr[cb][ds][1] = *(const float4*)(xb + (ch + 2) * 64 + ds * 16 + 8 * ND);
            }
        }
    };
    for (int ch2 = 0; ch2 < 16; ch2 += 2) {
        body(ch2,     0);
        body(ch2 + 1, 1);
    }

    // ---- row sum-of-squares: reduce over the 4 q-lanes ----
    ss0 += __shfl_xor_sync(0xffffffffu, ss0, 1);
    ss0 += __shfl_xor_sync(0xffffffffu, ss0, 2);
    ss1 += __shfl_xor_sync(0xffffffffu, ss1, 1);
    ss1 += __shfl_xor_sync(0xffffffffu, ss1, 2);
    if (q == 0) {
        ssrow[ar + gr]     = ss0;
        ssrow[ar + gr + 8] = ss1;
    }
    // ---- dump logits ----
#pragma unroll
    for (int nt = 0; nt < 8; nt++) {
        int r0 = ar + (lane >> 2);
        int c0 = nt * 8 + 2 * (lane & 3);
        lg[r0 * 66 + c0]           = acc[nt][0];
        lg[r0 * 66 + c0 + 1]       = acc[nt][1];
        lg[(r0 + 8) * 66 + c0]     = acc[nt][2];
        lg[(r0 + 8) * 66 + c0 + 1] = acc[nt][3];
    }
    __syncthreads();

    // ---- softmax: each warp does its 16 rows; lane owns cols (2l, 2l+1) ----
    float s0 = 0.f, s1 = 0.f;
    const int c0 = 2 * lane, c1 = 2 * lane + 1;
#pragma unroll 1
    for (int r = 0; r < 16; r++) {
        int rr = ar + r;
        float inv = 1.0f / fmaxf(sqrtf(ssrow[rr]), 1e-12f);
        float v0 = lg[rr * 66 + c0] * inv, v1 = lg[rr * 66 + c1] * inv;
        float mx = fmaxf(v0, v1);
#pragma unroll
        for (int o = 16; o > 0; o >>= 1) mx = fmaxf(mx, __shfl_xor_sync(0xffffffffu, mx, o));
        float e0 = expf(v0 - mx), e1 = expf(v1 - mx);
        float sm = e0 + e1;
#pragma unroll
        for (int o = 16; o > 0; o >>= 1) sm += __shfl_xor_sync(0xffffffffu, sm, o);
        float is = 1.0f / sm;
        float p0 = e0 * is, p1 = e1 * is;
        s0 += p0; s1 += p1;
        __nv_bfloat162 h;                    // store p * inv_m  (normalization folded in)
        h.x = __float2bfloat16_rn(p0 * inv);
        h.y = __float2bfloat16_rn(p1 * inv);
        ((__nv_bfloat162*)(g_a + (size_t)(m0 + rr) * NK))[lane] = h;
    }
    atomicAdd(&sas[c0], s0);
    atomicAdd(&sas[c1], s1);
    __syncthreads();
    if (tid < 64) atomicAdd(&g_asum[b * NK + tid], sas[tid]);
}

// ============ kernel: vlad[b] tile = A'^T X - asum*cent, + sumsq partials ============
// grid (8 d-tiles, 32 b) = 256 CTAs, all resident (2/SM). Full M=2048 per CTA,
// 2-stage cp.async double buffering. Epilogue: subtract asum*centroid, write
// final-unscaled fp32, and per-k-row sumsq partial for this d-tile (smem
// atomicAdd with exactly 2 contributors -> deterministic).
//
// dyn smem: at[2] 9216 ea @0 | xt[2] 17408 ea @18432 | ssq_s[64] f32 @53248
#define VL_SMEM 53504
__global__ __launch_bounds__(256, 2) void k_vlad(const float* __restrict__ cent) {
    extern __shared__ __align__(16) unsigned char dsm[];
    __nv_bfloat16* at[2] = { (__nv_bfloat16*)dsm,           (__nv_bfloat16*)(dsm + 9216) };
    __nv_bfloat16* xt[2] = { (__nv_bfloat16*)(dsm + 18432), (__nv_bfloat16*)(dsm + 35840) };
    float* ssq_s = (float*)(dsm + 53248);

    const int tid = threadIdx.x, lane = tid & 31, warp = tid >> 5;
    const int b  = blockIdx.y;
    const int d0 = blockIdx.x * 128;
    const int wk = (warp & 3) * 16;     // k-row base for this warp
    const int wd = (warp >> 2) * 64;    // d-col base within tile

    if (tid < 64) ssq_s[tid] = 0.f;

    const size_t rowbase = (size_t)b * NM;

    float acc[8][4];
#pragma unroll
    for (int i = 0; i < 8; i++)
#pragma unroll
        for (int j = 0; j < 4; j++) acc[i][j] = 0.f;

    auto issue = [&](int mc, int s) {
        const size_t mrow = rowbase + mc * 64;
#pragma unroll
        for (int it = 0; it < 2; it++) {     // a tile: 64 m x 64 k
            int idx = tid + it * 256;
            int r = idx >> 3, c = idx & 7;
            cp16(s2u(at[s] + r * 72 + c * 8), g_a + (mrow + r) * NK + c * 8);
        }
#pragma unroll
        for (int it = 0; it < 4; it++) {     // x tile: 64 m x 128 d
            int idx = tid + it * 256;
            int r = idx >> 4, c = idx & 15;
            cp16(s2u(xt[s] + r * 136 + c * 8), g_x16 + (mrow + r) * ND + d0 + c * 8);
        }
        cp_commit();
    };

    issue(0, 0);
    for (int mc = 0; mc < 32; mc++) {
        if (mc + 1 < 32) { issue(mc + 1, (mc + 1) & 1); cp_wait<1>(); }
        else             { cp_wait<0>(); }
        __syncthreads();
        const int s = mc & 1;
#pragma unroll
        for (int ms = 0; ms < 4; ms++) {
            int mb = ms * 16;
            unsigned a0, a1, a2, a3;
            {   // A = a^T (k x m) from [m][k] storage -> ldmatrix.trans
                int i = lane & 7;
                int r = mb + i + ((lane >> 4) & 1) * 8;
                int c = wk + ((lane >> 3) & 1) * 8;
                ldsm_x4t(a0, a1, a2, a3, s2u(at[s] + r * 72 + c));
            }
#pragma unroll
            for (int nt = 0; nt < 8; nt += 2) {
                unsigned b0, b1, b2, b3;
                int r = mb + (lane & 7) + ((lane >> 3) & 1) * 8;
                int c = wd + nt * 8 + ((lane >> 4) & 1) * 8;
                ldsm_x4t(b0, b1, b2, b3, s2u(xt[s] + r * 136 + c));
                mma16816(acc[nt],     a0, a1, a2, a3, b0, b1);
                mma16816(acc[nt + 1], a0, a1, a2, a3, b2, b3);
            }
        }
        __syncthreads();
    }

    // ---- epilogue: subtract asum*centroid, write fp32, sumsq partials ----
    const int k0 = wk + (lane >> 2);
    const float as0 = g_asum[b * NK + k0];
    const float as1 = g_asum[b * NK + k0 + 8];
    float* vb = g_vfin + ((size_t)b * NK) * ND;
    float sq0 = 0.f, sq1 = 0.f;
#pragma unroll
    for (int nt = 0; nt < 8; nt++) {
        int dd = d0 + wd + nt * 8 + 2 * (lane & 3);
        float2 c0 = *(const float2*)(cent + (size_t)k0 * ND + dd);
        float2 c1 = *(const float2*)(cent + (size_t)(k0 + 8) * ND + dd);
        float v00 = acc[nt][0] - as0 * c0.x;
        float v01 = acc[nt][1] - as0 * c0.y;
        float v10 = acc[nt][2] - as1 * c1.x;
        float v11 = acc[nt][3] - as1 * c1.y;
        sq0 += v00 * v00 + v01 * v01;
        sq1 += v10 * v10 + v11 * v11;
        *(float2*)(vb + (size_t)k0 * ND + dd)       = make_float2(v00, v01);
        *(float2*)(vb + (size_t)(k0 + 8) * ND + dd) = make_float2(v10, v11);
    }
    // reduce over the 4 lanes sharing a row
    sq0 += __shfl_xor_sync(0xffffffffu, sq0, 1);
    sq0 += __shfl_xor_sync(0xffffffffu, sq0, 2);
    sq1 += __shfl_xor_sync(0xffffffffu, sq1, 1);
    sq1 += __shfl_xor_sync(0xffffffffu, sq1, 2);
    if ((lane & 3) == 0) {        // 2 warps (wd halves) contribute per row slot
        atomicAdd(&ssq_s[k0], sq0);
        atomicAdd(&ssq_s[k0 + 8], sq1);
    }
    __syncthreads();
    if (tid < 64)
        g_ssq[(b * NK + tid) * 8 + blockIdx.x] = ssq_s[tid];
}

// ---------------- kernel: per-(b,k) scale = 0.125/||v|| (global norm = 8) ----------------
__global__ __launch_bounds__(256) void k_scale(float* __restrict__ out) {
    const int bk = blockIdx.x;           // b*64 + k
    const int tid = threadIdx.x;
    float tot = 0.f;
#pragma unroll
    for (int j = 0; j < 8; j++) tot += g_ssq[bk * 8 + j];   // fixed order: deterministic
    const float inv = 0.125f / fmaxf(sqrtf(tot), 1e-12f);
    const float* vr = g_vfin + (size_t)bk * ND;
    float* op = out + (size_t)bk * ND;
#pragma unroll
    for (int i = 0; i < 4; i++) {
        int d = tid + i * 256;
        op[d] = vr[d] * inv;
    }
}

// ---------------- launch ----------------
extern "C" void kernel_launch(void* const* d_in, const int* in_sizes, int n_in,
                              void* d_out, int out_size) {
    const float* x    = (const float*)d_in[0];
    const float* W    = (const float*)d_in[1];
    const float* cent = (const float*)d_in[2];
    float* out = (float*)d_out;

    static int configured = 0;
    if (!configured) {
        cudaFuncSetAttribute(k_nl,   cudaFuncAttributeMaxDynamicSharedMemorySize, NL_SMEM);
        cudaFuncSetAttribute(k_vlad, cudaFuncAttributeMaxDynamicSharedMemorySize, VL_SMEM);
        configured = 1;
    }

    k_wconv<<<256, 256>>>(W);
    k_nl   <<<512, 256, NL_SMEM>>>(x);
    k_vlad <<<dim3(8, 32), 256, VL_SMEM>>>(cent);
    k_scale<<<2048, 256>>>(out);
}

// round 9
// speedup vs baseline: 1.0412x; 1.0412x over previous
#include <cuda_runtime.h>
#include <cuda_bf16.h>
#include <cstdint>

#define NB 32
#define NM 2048
#define ND 1024
#define NK 64
#define BM (NB*NM)   // 65536 rows total

// ---------------- scratch (device globals; no allocs allowed) ----------------
__device__ __nv_bfloat16 g_x16[(size_t)BM * ND];       // 128 MB bf16(x) RAW (not normalized)
__device__ __nv_bfloat16 g_w16[NK * ND];               // W in bf16, k-PERMUTED within 16-groups
__device__ __nv_bfloat16 g_a[(size_t)BM * NK];         // p[m,k] * inv_m  (bf16)
__device__ float         g_asum[NB * NK];              // sum_m p[b,m,k]  (unscaled)
__device__ float         g_vfin[(size_t)NB * NK * ND]; // centroid-subtracted vlad (unscaled)
__device__ float         g_ssq[NB * NK * 16];          // per-(b,k) sumsq partials, 16 d-tiles

// ---------------- helpers ----------------
static __device__ __forceinline__ unsigned s2u(const void* p) {
    return (unsigned)__cvta_generic_to_shared(p);
}
static __device__ __forceinline__ void cp16(unsigned dst, const void* src) {
    asm volatile("cp.async.cg.shared.global [%0], [%1], 16;\n" :: "r"(dst), "l"(src));
}
static __device__ __forceinline__ void cp_commit() {
    asm volatile("cp.async.commit_group;\n");
}
template<int N> static __device__ __forceinline__ void cp_wait() {
    asm volatile("cp.async.wait_group %0;\n" :: "n"(N));
}
static __device__ __forceinline__ void ldsm_x4(unsigned& r0, unsigned& r1, unsigned& r2, unsigned& r3, unsigned a) {
    asm volatile("ldmatrix.sync.aligned.m8n8.x4.shared.b16 {%0,%1,%2,%3}, [%4];"
                 : "=r"(r0), "=r"(r1), "=r"(r2), "=r"(r3) : "r"(a));
}
static __device__ __forceinline__ void ldsm_x4t(unsigned& r0, unsigned& r1, unsigned& r2, unsigned& r3, unsigned a) {
    asm volatile("ldmatrix.sync.aligned.m8n8.x4.trans.shared.b16 {%0,%1,%2,%3}, [%4];"
                 : "=r"(r0), "=r"(r1), "=r"(r2), "=r"(r3) : "r"(a));
}
static __device__ __forceinline__ void mma16816(float* c,
        unsigned a0, unsigned a1, unsigned a2, unsigned a3, unsigned b0, unsigned b1) {
    asm volatile("mma.sync.aligned.m16n8k16.row.col.f32.bf16.bf16.f32 "
                 "{%0,%1,%2,%3}, {%4,%5,%6,%7}, {%8,%9}, {%0,%1,%2,%3};"
                 : "+f"(c[0]), "+f"(c[1]), "+f"(c[2]), "+f"(c[3])
                 : "r"(a0), "r"(a1), "r"(a2), "r"(a3), "r"(b0), "r"(b1));
}
static __device__ __forceinline__ unsigned packbf(float a, float b) {
    __nv_bfloat162 h;
    h.x = __float2bfloat16_rn(a);
    h.y = __float2bfloat16_rn(b);
    return *reinterpret_cast<unsigned*>(&h);
}

// ---------------- kernel 0: W -> bf16 (k-permuted), zero a_sum ----------------
// Permutation within each 16-col group: logical j -> slot 2*(j>>2)+(j&1)+((j&2)?8:0),
// matching A-fragments built straight from float4 LDGs.
__global__ __launch_bounds__(256) void k_wconv(const float* __restrict__ W) {
    int i = blockIdx.x * 256 + threadIdx.x;       // grid 256 -> exactly NK*ND
    int kl = i & (ND - 1);
    int j  = kl & 15;
    int sl = 2 * (j >> 2) + (j & 1) + ((j & 2) ? 8 : 0);
    int oc = (kl & ~15) | sl;
    g_w16[(i & ~(ND - 1)) | oc] = __float2bfloat16_rn(W[i]);
    if (i < NB * NK) g_asum[i] = 0.f;
}

// ============ fused: x->bf16 + logits GEMM + row-norm + softmax + a_sum ============
// (R7-proven version, unchanged.) 128 rows per block (grid 512). A-operand
// fragments built directly from x LDG.128 registers; raw bf16 streamed to g_x16.
// W tiles double-buffered via cp.async, consumed with ldsm_x4.
//
// dyn smem layout (bytes):
//   wt[2] [64][72] bf16 @ 0      18432
//   lg    [128][66] f32 @ 18432  33792
//   ssrow [128]     f32 @ 52224    512
//   sas   [64]      f32 @ 52736    256
#define NL_SMEM 52992
__global__ __launch_bounds__(256, 2) void k_nl(const float* __restrict__ x) {
    extern __shared__ __align__(16) unsigned char dsm[];
    __nv_bfloat16* wt[2] = { (__nv_bfloat16*)dsm, (__nv_bfloat16*)(dsm + 9216) };
    float* lg    = (float*)(dsm + 18432);
    float* ssrow = (float*)(dsm + 52224);
    float* sas   = (float*)(dsm + 52736);

    const int tid = threadIdx.x, lane = tid & 31, warp = tid >> 5;
    const int m0 = blockIdx.x * 128;
    const int b  = m0 >> 11;

    if (tid < 64) sas[tid] = 0.f;

    const int gr = lane >> 2, q = lane & 3;
    const int ar = warp * 16;                       // warp's 16 m-rows
    const size_t row0 = (size_t)(m0 + ar + gr);     // lo row; hi row = row0 + 8

    float4 xr[2][4][2];
    float ss0 = 0.f, ss1 = 0.f;

    float acc[8][4];
#pragma unroll
    for (int i = 0; i < 8; i++)
#pragma unroll
        for (int j = 0; j < 4; j++) acc[i][j] = 0.f;

    auto ldw = [&](int ch, int s) {
#pragma unroll
        for (int it = 0; it < 2; it++) {
            int idx = tid + it * 256;
            int r = idx >> 3, c = idx & 7;
            cp16(s2u(wt[s] + r * 72 + c * 8), g_w16 + (size_t)r * ND + ch * 64 + c * 8);
        }
        cp_commit();
    };

    const float* xb = x + row0 * ND + q * 4;

    // ---- prologue ----
#pragma unroll
    for (int ds = 0; ds < 4; ds++) {
        xr[0][ds][0] = *(const float4*)(xb + ds * 16);
        xr[0][ds][1] = *(const float4*)(xb + ds * 16 + 8 * ND);
    }
    ldw(0, 0);
    ldw(1, 1);
#pragma unroll
    for (int ds = 0; ds < 4; ds++) {
        xr[1][ds][0] = *(const float4*)(xb + 64 + ds * 16);
        xr[1][ds][1] = *(const float4*)(xb + 64 + ds * 16 + 8 * ND);
    }
    cp_wait<1>();
    __syncthreads();

    // ---- main loop: ch unrolled by 2 so buffer indices are literals ----
    auto body = [&](int ch, int cb) {
#pragma unroll
        for (int ds = 0; ds < 4; ds++) {
            float4 f0 = xr[cb][ds][0];
            float4 f1 = xr[cb][ds][1];
            ss0 += f0.x * f0.x + f0.y * f0.y + f0.z * f0.z + f0.w * f0.w;
            ss1 += f1.x * f1.x + f1.y * f1.y + f1.z * f1.z + f1.w * f1.w;
            unsigned a0 = packbf(f0.x, f0.y), a2 = packbf(f0.z, f0.w);
            unsigned a1 = packbf(f1.x, f1.y), a3 = packbf(f1.z, f1.w);
            {   // raw bf16 out (natural order) for k_vlad
                __nv_bfloat16* gx = g_x16 + row0 * ND + ch * 64 + ds * 16 + q * 4;
                uint2 u0; u0.x = a0; u0.y = a2;
                uint2 u1; u1.x = a1; u1.y = a3;
                *(uint2*)gx            = u0;
                *(uint2*)(gx + 8 * ND) = u1;
            }
#pragma unroll
            for (int nt = 0; nt < 8; nt += 2) {
                unsigned b0, b1, b2, b3;
                int r = nt * 8 + (lane & 7) + ((lane >> 4) & 1) * 8;
                int c = ds * 16 + ((lane >> 3) & 1) * 8;
                ldsm_x4(b0, b1, b2, b3, s2u(wt[cb] + r * 72 + c));
                mma16816(acc[nt],     a0, a1, a2, a3, b0, b1);
                mma16816(acc[nt + 1], a0, a1, a2, a3, b2, b3);
            }
        }
        if (ch + 2 < 16) {
#pragma unroll
            for (int ds = 0; ds < 4; ds++) {
                xr[cb][ds][0] = *(const float4*)(xb + (ch + 2) * 64 + ds * 16);
                xr[cb][ds][1] = *(const float4*)(xb + (ch + 2) * 64 + ds * 16 + 8 * ND);
            }
        }
        __syncthreads();                 // all reads of wt[cb] complete
        if (ch + 2 < 16) { ldw(ch + 2, cb); cp_wait<1>(); }
        else             cp_wait<0>();
        __syncthreads();                 // wt writes visible
    };
    for (int ch2 = 0; ch2 < 16; ch2 += 2) {
        body(ch2,     0);
        body(ch2 + 1, 1);
    }

    // ---- row sum-of-squares: reduce over the 4 q-lanes ----
    ss0 += __shfl_xor_sync(0xffffffffu, ss0, 1);
    ss0 += __shfl_xor_sync(0xffffffffu, ss0, 2);
    ss1 += __shfl_xor_sync(0xffffffffu, ss1, 1);
    ss1 += __shfl_xor_sync(0xffffffffu, ss1, 2);
    if (q == 0) {
        ssrow[ar + gr]     = ss0;
        ssrow[ar + gr + 8] = ss1;
    }
    // ---- dump logits ----
#pragma unroll
    for (int nt = 0; nt < 8; nt++) {
        int r0 = ar + (lane >> 2);
        int c0 = nt * 8 + 2 * (lane & 3);
        lg[r0 * 66 + c0]           = acc[nt][0];
        lg[r0 * 66 + c0 + 1]       = acc[nt][1];
        lg[(r0 + 8) * 66 + c0]     = acc[nt][2];
        lg[(r0 + 8) * 66 + c0 + 1] = acc[nt][3];
    }
    __syncthreads();

    // ---- softmax: each warp does its 16 rows; lane owns cols (2l, 2l+1) ----
    float s0 = 0.f, s1 = 0.f;
    const int c0 = 2 * lane, c1 = 2 * lane + 1;
#pragma unroll 1
    for (int r = 0; r < 16; r++) {
        int rr = ar + r;
        float inv = 1.0f / fmaxf(sqrtf(ssrow[rr]), 1e-12f);
        float v0 = lg[rr * 66 + c0] * inv, v1 = lg[rr * 66 + c1] * inv;
        float mx = fmaxf(v0, v1);
#pragma unroll
        for (int o = 16; o > 0; o >>= 1) mx = fmaxf(mx, __shfl_xor_sync(0xffffffffu, mx, o));
        float e0 = expf(v0 - mx), e1 = expf(v1 - mx);
        float sm = e0 + e1;
#pragma unroll
        for (int o = 16; o > 0; o >>= 1) sm += __shfl_xor_sync(0xffffffffu, sm, o);
        float is = 1.0f / sm;
        float p0 = e0 * is, p1 = e1 * is;
        s0 += p0; s1 += p1;
        __nv_bfloat162 h;                    // store p * inv_m  (normalization folded in)
        h.x = __float2bfloat16_rn(p0 * inv);
        h.y = __float2bfloat16_rn(p1 * inv);
        ((__nv_bfloat162*)(g_a + (size_t)(m0 + rr) * NK))[lane] = h;
    }
    atomicAdd(&sas[c0], s0);
    atomicAdd(&sas[c1], s1);
    __syncthreads();
    if (tid < 64) atomicAdd(&g_asum[b * NK + tid], sas[tid]);
}

// ============ kernel: vlad (b, 64-d-slice) = A'^T X - asum*cent, fused epilogue ============
// grid (16 d-tiles, 32 b) = 512 CTAs, 4/SM -> single wave. Full M=2048 (32 chunks),
// 2-stage cp.async double buffering. Each CTA owns its output slice completely:
// subtract asum*centroid, write final-unscaled fp32, per-k sumsq partial for this
// d-tile (smem atomicAdd with exactly 2 contributors -> deterministic).
//
// dyn smem: at[2] 9216 ea @0 | xt[2] 9216 ea @18432 | ssq_s[64] f32 @36864
#define VL_SMEM 37120
__global__ __launch_bounds__(256, 4) void k_vlad(const float* __restrict__ cent) {
    extern __shared__ __align__(16) unsigned char dsm[];
    __nv_bfloat16* at[2] = { (__nv_bfloat16*)dsm,           (__nv_bfloat16*)(dsm + 9216) };
    __nv_bfloat16* xt[2] = { (__nv_bfloat16*)(dsm + 18432), (__nv_bfloat16*)(dsm + 27648) };
    float* ssq_s = (float*)(dsm + 36864);

    const int tid = threadIdx.x, lane = tid & 31, warp = tid >> 5;
    const int b  = blockIdx.y;
    const int d0 = blockIdx.x * 64;
    const int wk = (warp & 3) * 16;     // k-row base for this warp
    const int wd = (warp >> 2) * 32;    // d-col base within 64-wide tile

    if (tid < 64) ssq_s[tid] = 0.f;

    const size_t rowbase = (size_t)b * NM;

    float acc[4][4];
#pragma unroll
    for (int i = 0; i < 4; i++)
#pragma unroll
        for (int j = 0; j < 4; j++) acc[i][j] = 0.f;

    auto issue = [&](int mc, int s) {
        const size_t mrow = rowbase + mc * 64;
#pragma unroll
        for (int it = 0; it < 2; it++) {     // a tile: 64 m x 64 k
            int idx = tid + it * 256;
            int r = idx >> 3, c = idx & 7;
            cp16(s2u(at[s] + r * 72 + c * 8), g_a + (mrow + r) * NK + c * 8);
        }
#pragma unroll
        for (int it = 0; it < 2; it++) {     // x tile: 64 m x 64 d
            int idx = tid + it * 256;
            int r = idx >> 3, c = idx & 7;
            cp16(s2u(xt[s] + r * 72 + c * 8), g_x16 + (mrow + r) * ND + d0 + c * 8);
        }
        cp_commit();
    };

    issue(0, 0);
    for (int mc = 0; mc < 32; mc++) {
        if (mc + 1 < 32) { issue(mc + 1, (mc + 1) & 1); cp_wait<1>(); }
        else             { cp_wait<0>(); }
        __syncthreads();
        const int s = mc & 1;
#pragma unroll
        for (int ms = 0; ms < 4; ms++) {
            int mb = ms * 16;
            unsigned a0, a1, a2, a3;
            {   // A = a^T (k x m) from [m][k] storage -> ldmatrix.trans
                int i = lane & 7;
                int r = mb + i + ((lane >> 4) & 1) * 8;
                int c = wk + ((lane >> 3) & 1) * 8;
                ldsm_x4t(a0, a1, a2, a3, s2u(at[s] + r * 72 + c));
            }
#pragma unroll
            for (int nt = 0; nt < 4; nt += 2) {
                unsigned b0, b1, b2, b3;
                int r = mb + (lane & 7) + ((lane >> 3) & 1) * 8;
                int c = wd + nt * 8 + ((lane >> 4) & 1) * 8;
                ldsm_x4t(b0, b1, b2, b3, s2u(xt[s] + r * 72 + c));
                mma16816(acc[nt],     a0, a1, a2, a3, b0, b1);
                mma16816(acc[nt + 1], a0, a1, a2, a3, b2, b3);
            }
        }
        __syncthreads();
    }

    // ---- fused epilogue: subtract asum*centroid, write fp32, sumsq partials ----
    const int k0 = wk + (lane >> 2);
    const float as0 = g_asum[b * NK + k0];
    const float as1 = g_asum[b * NK + k0 + 8];
    float* vb = g_vfin + ((size_t)b * NK) * ND;
    float sq0 = 0.f, sq1 = 0.f;
#pragma unroll
    for (int nt = 0; nt < 4; nt++) {
        int dd = d0 + wd + nt * 8 + 2 * (lane & 3);
        float2 c0 = *(const float2*)(cent + (size_t)k0 * ND + dd);
        float2 c1 = *(const float2*)(cent + (size_t)(k0 + 8) * ND + dd);
        float v00 = acc[nt][0] - as0 * c0.x;
        float v01 = acc[nt][1] - as0 * c0.y;
        float v10 = acc[nt][2] - as1 * c1.x;
        float v11 = acc[nt][3] - as1 * c1.y;
        sq0 += v00 * v00 + v01 * v01;
        sq1 += v10 * v10 + v11 * v11;
        *(float2*)(vb + (size_t)k0 * ND + dd)       = make_float2(v00, v01);
        *(float2*)(vb + (size_t)(k0 + 8) * ND + dd) = make_float2(v10, v11);
    }
    // reduce over the 4 lanes sharing a k-row
    sq0 += __shfl_xor_sync(0xffffffffu, sq0, 1);
    sq0 += __shfl_xor_sync(0xffffffffu, sq0, 2);
    sq1 += __shfl_xor_sync(0xffffffffu, sq1, 1);
    sq1 += __shfl_xor_sync(0xffffffffu, sq1, 2);
    if ((lane & 3) == 0) {        // 2 warps (wd halves) contribute per row slot
        atomicAdd(&ssq_s[k0], sq0);
        atomicAdd(&ssq_s[k0 + 8], sq1);
    }
    __syncthreads();
    if (tid < 64)
        g_ssq[(b * NK + tid) * 16 + blockIdx.x] = ssq_s[tid];
}

// ---------------- kernel: per-(b,k) scale = 0.125/||v|| (global norm = 8) ----------------
__global__ __launch_bounds__(256) void k_scale(float* __restrict__ out) {
    const int bk = blockIdx.x;           // b*64 + k
    const int tid = threadIdx.x;
    float tot = 0.f;
#pragma unroll
    for (int j = 0; j < 16; j++) tot += g_ssq[bk * 16 + j];   // fixed order: deterministic
    const float inv = 0.125f / fmaxf(sqrtf(tot), 1e-12f);
    const float* vr = g_vfin + (size_t)bk * ND;
    float* op = out + (size_t)bk * ND;
#pragma unroll
    for (int i = 0; i < 4; i++) {
        int d = tid + i * 256;
        op[d] = vr[d] * inv;
    }
}

// ---------------- launch ----------------
extern "C" void kernel_launch(void* const* d_in, const int* in_sizes, int n_in,
                              void* d_out, int out_size) {
    const float* x    = (const float*)d_in[0];
    const float* W    = (const float*)d_in[1];
    const float* cent = (const float*)d_in[2];
    float* out = (float*)d_out;

    static int configured = 0;
    if (!configured) {
        cudaFuncSetAttribute(k_nl,   cudaFuncAttributeMaxDynamicSharedMemorySize, NL_SMEM);
        cudaFuncSetAttribute(k_vlad, cudaFuncAttributeMaxDynamicSharedMemorySize, VL_SMEM);
        configured = 1;
    }

    k_wconv<<<256, 256>>>(W);
    k_nl   <<<512, 256, NL_SMEM>>>(x);
    k_vlad <<<dim3(16, 32), 256, VL_SMEM>>>(cent);
    k_scale<<<2048, 256>>>(out);
}

// round 10
// speedup vs baseline: 1.1101x; 1.0662x over previous
#include <cuda_runtime.h>
#include <cuda_bf16.h>
#include <cstdint>

#define NB 32
#define NM 2048
#define ND 1024
#define NK 64
#define BM (NB*NM)   // 65536 rows total

// ---------------- scratch (device globals; no allocs allowed) ----------------
__device__ __nv_bfloat16 g_x16[(size_t)BM * ND];       // 128 MB bf16(x) RAW (not normalized)
__device__ __nv_bfloat16 g_w16[NK * ND];               // W in bf16, k-PERMUTED within 16-groups
__device__ __nv_bfloat16 g_a[(size_t)BM * NK];         // p[m,k] * inv_m  (bf16)
__device__ float         g_asum[NB * NK];              // sum_m p[b,m,k]  (unscaled)
__device__ float         g_vfin[(size_t)NB * NK * ND]; // centroid-subtracted vlad (unscaled)
__device__ float         g_ssq[NB * NK * 8];           // per-(b,k) sumsq partials, 8 d-tiles

// ---------------- helpers ----------------
static __device__ __forceinline__ unsigned s2u(const void* p) {
    return (unsigned)__cvta_generic_to_shared(p);
}
static __device__ __forceinline__ void cp16(unsigned dst, const void* src) {
    asm volatile("cp.async.cg.shared.global [%0], [%1], 16;\n" :: "r"(dst), "l"(src));
}
static __device__ __forceinline__ void cp_commit() {
    asm volatile("cp.async.commit_group;\n");
}
template<int N> static __device__ __forceinline__ void cp_wait() {
    asm volatile("cp.async.wait_group %0;\n" :: "n"(N));
}
static __device__ __forceinline__ void ldsm_x4(unsigned& r0, unsigned& r1, unsigned& r2, unsigned& r3, unsigned a) {
    asm volatile("ldmatrix.sync.aligned.m8n8.x4.shared.b16 {%0,%1,%2,%3}, [%4];"
                 : "=r"(r0), "=r"(r1), "=r"(r2), "=r"(r3) : "r"(a));
}
static __device__ __forceinline__ void ldsm_x4t(unsigned& r0, unsigned& r1, unsigned& r2, unsigned& r3, unsigned a) {
    asm volatile("ldmatrix.sync.aligned.m8n8.x4.trans.shared.b16 {%0,%1,%2,%3}, [%4];"
                 : "=r"(r0), "=r"(r1), "=r"(r2), "=r"(r3) : "r"(a));
}
static __device__ __forceinline__ void mma16816(float* c,
        unsigned a0, unsigned a1, unsigned a2, unsigned a3, unsigned b0, unsigned b1) {
    asm volatile("mma.sync.aligned.m16n8k16.row.col.f32.bf16.bf16.f32 "
                 "{%0,%1,%2,%3}, {%4,%5,%6,%7}, {%8,%9}, {%0,%1,%2,%3};"
                 : "+f"(c[0]), "+f"(c[1]), "+f"(c[2]), "+f"(c[3])
                 : "r"(a0), "r"(a1), "r"(a2), "r"(a3), "r"(b0), "r"(b1));
}
static __device__ __forceinline__ unsigned packbf(float a, float b) {
    __nv_bfloat162 h;
    h.x = __float2bfloat16_rn(a);
    h.y = __float2bfloat16_rn(b);
    return *reinterpret_cast<unsigned*>(&h);
}

// ---------------- kernel 0: W -> bf16 (k-permuted), zero a_sum ----------------
// Permutation within each 16-col group: logical j -> slot 2*(j>>2)+(j&1)+((j&2)?8:0),
// matching A-fragments built straight from float4 LDGs.
__global__ __launch_bounds__(256) void k_wconv(const float* __restrict__ W) {
    int i = blockIdx.x * 256 + threadIdx.x;       // grid 256 -> exactly NK*ND
    int kl = i & (ND - 1);
    int j  = kl & 15;
    int sl = 2 * (j >> 2) + (j & 1) + ((j & 2) ? 8 : 0);
    int oc = (kl & ~15) | sl;
    g_w16[(i & ~(ND - 1)) | oc] = __float2bfloat16_rn(W[i]);
    if (i < NB * NK) g_asum[i] = 0.f;
}

// ============ fused: x->bf16 + logits GEMM + row-norm + softmax + a_sum ============
// (R7-proven version, unchanged.) 128 rows per block (grid 512). A-operand
// fragments built directly from x LDG.128 registers; raw bf16 streamed to g_x16.
// W tiles double-buffered via cp.async, consumed with ldsm_x4.
//
// dyn smem layout (bytes):
//   wt[2] [64][72] bf16 @ 0      18432
//   lg    [128][66] f32 @ 18432  33792
//   ssrow [128]     f32 @ 52224    512
//   sas   [64]      f32 @ 52736    256
#define NL_SMEM 52992
__global__ __launch_bounds__(256, 2) void k_nl(const float* __restrict__ x) {
    extern __shared__ __align__(16) unsigned char dsm[];
    __nv_bfloat16* wt[2] = { (__nv_bfloat16*)dsm, (__nv_bfloat16*)(dsm + 9216) };
    float* lg    = (float*)(dsm + 18432);
    float* ssrow = (float*)(dsm + 52224);
    float* sas   = (float*)(dsm + 52736);

    const int tid = threadIdx.x, lane = tid & 31, warp = tid >> 5;
    const int m0 = blockIdx.x * 128;
    const int b  = m0 >> 11;

    if (tid < 64) sas[tid] = 0.f;

    const int gr = lane >> 2, q = lane & 3;
    const int ar = warp * 16;                       // warp's 16 m-rows
    const size_t row0 = (size_t)(m0 + ar + gr);     // lo row; hi row = row0 + 8

    float4 xr[2][4][2];
    float ss0 = 0.f, ss1 = 0.f;

    float acc[8][4];
#pragma unroll
    for (int i = 0; i < 8; i++)
#pragma unroll
        for (int j = 0; j < 4; j++) acc[i][j] = 0.f;

    auto ldw = [&](int ch, int s) {
#pragma unroll
        for (int it = 0; it < 2; it++) {
            int idx = tid + it * 256;
            int r = idx >> 3, c = idx & 7;
            cp16(s2u(wt[s] + r * 72 + c * 8), g_w16 + (size_t)r * ND + ch * 64 + c * 8);
        }
        cp_commit();
    };

    const float* xb = x + row0 * ND + q * 4;

    // ---- prologue ----
#pragma unroll
    for (int ds = 0; ds < 4; ds++) {
        xr[0][ds][0] = *(const float4*)(xb + ds * 16);
        xr[0][ds][1] = *(const float4*)(xb + ds * 16 + 8 * ND);
    }
    ldw(0, 0);
    ldw(1, 1);
#pragma unroll
    for (int ds = 0; ds < 4; ds++) {
        xr[1][ds][0] = *(const float4*)(xb + 64 + ds * 16);
        xr[1][ds][1] = *(const float4*)(xb + 64 + ds * 16 + 8 * ND);
    }
    cp_wait<1>();
    __syncthreads();

    // ---- main loop: ch unrolled by 2 so buffer indices are literals ----
    auto body = [&](int ch, int cb) {
#pragma unroll
        for (int ds = 0; ds < 4; ds++) {
            float4 f0 = xr[cb][ds][0];
            float4 f1 = xr[cb][ds][1];
            ss0 += f0.x * f0.x + f0.y * f0.y + f0.z * f0.z + f0.w * f0.w;
            ss1 += f1.x * f1.x + f1.y * f1.y + f1.z * f1.z + f1.w * f1.w;
            unsigned a0 = packbf(f0.x, f0.y), a2 = packbf(f0.z, f0.w);
            unsigned a1 = packbf(f1.x, f1.y), a3 = packbf(f1.z, f1.w);
            {   // raw bf16 out (natural order) for k_vlad
                __nv_bfloat16* gx = g_x16 + row0 * ND + ch * 64 + ds * 16 + q * 4;
                uint2 u0; u0.x = a0; u0.y = a2;
                uint2 u1; u1.x = a1; u1.y = a3;
                *(uint2*)gx            = u0;
                *(uint2*)(gx + 8 * ND) = u1;
            }
#pragma unroll
            for (int nt = 0; nt < 8; nt += 2) {
                unsigned b0, b1, b2, b3;
                int r = nt * 8 + (lane & 7) + ((lane >> 4) & 1) * 8;
                int c = ds * 16 + ((lane >> 3) & 1) * 8;
                ldsm_x4(b0, b1, b2, b3, s2u(wt[cb] + r * 72 + c));
                mma16816(acc[nt],     a0, a1, a2, a3, b0, b1);
                mma16816(acc[nt + 1], a0, a1, a2, a3, b2, b3);
            }
        }
        if (ch + 2 < 16) {
#pragma unroll
            for (int ds = 0; ds < 4; ds++) {
                xr[cb][ds][0] = *(const float4*)(xb + (ch + 2) * 64 + ds * 16);
                xr[cb][ds][1] = *(const float4*)(xb + (ch + 2) * 64 + ds * 16 + 8 * ND);
            }
        }
        __syncthreads();                 // all reads of wt[cb] complete
        if (ch + 2 < 16) { ldw(ch + 2, cb); cp_wait<1>(); }
        else             cp_wait<0>();
        __syncthreads();                 // wt writes visible
    };
    for (int ch2 = 0; ch2 < 16; ch2 += 2) {
        body(ch2,     0);
        body(ch2 + 1, 1);
    }

    // ---- row sum-of-squares: reduce over the 4 q-lanes ----
    ss0 += __shfl_xor_sync(0xffffffffu, ss0, 1);
    ss0 += __shfl_xor_sync(0xffffffffu, ss0, 2);
    ss1 += __shfl_xor_sync(0xffffffffu, ss1, 1);
    ss1 += __shfl_xor_sync(0xffffffffu, ss1, 2);
    if (q == 0) {
        ssrow[ar + gr]     = ss0;
        ssrow[ar + gr + 8] = ss1;
    }
    // ---- dump logits ----
#pragma unroll
    for (int nt = 0; nt < 8; nt++) {
        int r0 = ar + (lane >> 2);
        int c0 = nt * 8 + 2 * (lane & 3);
        lg[r0 * 66 + c0]           = acc[nt][0];
        lg[r0 * 66 + c0 + 1]       = acc[nt][1];
        lg[(r0 + 8) * 66 + c0]     = acc[nt][2];
        lg[(r0 + 8) * 66 + c0 + 1] = acc[nt][3];
    }
    __syncthreads();

    // ---- softmax: each warp does its 16 rows; lane owns cols (2l, 2l+1) ----
    float s0 = 0.f, s1 = 0.f;
    const int c0 = 2 * lane, c1 = 2 * lane + 1;
#pragma unroll 1
    for (int r = 0; r < 16; r++) {
        int rr = ar + r;
        float inv = 1.0f / fmaxf(sqrtf(ssrow[rr]), 1e-12f);
        float v0 = lg[rr * 66 + c0] * inv, v1 = lg[rr * 66 + c1] * inv;
        float mx = fmaxf(v0, v1);
#pragma unroll
        for (int o = 16; o > 0; o >>= 1) mx = fmaxf(mx, __shfl_xor_sync(0xffffffffu, mx, o));
        float e0 = expf(v0 - mx), e1 = expf(v1 - mx);
        float sm = e0 + e1;
#pragma unroll
        for (int o = 16; o > 0; o >>= 1) sm += __shfl_xor_sync(0xffffffffu, sm, o);
        float is = 1.0f / sm;
        float p0 = e0 * is, p1 = e1 * is;
        s0 += p0; s1 += p1;
        __nv_bfloat162 h;                    // store p * inv_m  (normalization folded in)
        h.x = __float2bfloat16_rn(p0 * inv);
        h.y = __float2bfloat16_rn(p1 * inv);
        ((__nv_bfloat162*)(g_a + (size_t)(m0 + rr) * NK))[lane] = h;
    }
    atomicAdd(&sas[c0], s0);
    atomicAdd(&sas[c1], s1);
    __syncthreads();
    if (tid < 64) atomicAdd(&g_asum[b * NK + tid], sas[tid]);
}

// ============ kernel: vlad[b] tile = A'^T X - asum*cent, fused epilogue ============
// (R8-proven k_vlad.) grid (8 d-tiles of 128, 32 b) = 256 CTAs, 2/SM. Full M=2048
// per CTA (32 chunks), 2-stage cp.async double buffering. Epilogue: subtract
// asum*centroid, write final-unscaled fp32, per-k sumsq partial for this d-tile
// (smem atomicAdd with exactly 2 contributors -> deterministic).
//
// dyn smem: at[2] 9216 ea @0 | xt[2] 17408 ea @18432 | ssq_s[64] f32 @53248
#define VL_SMEM 53504
__global__ __launch_bounds__(256, 2) void k_vlad(const float* __restrict__ cent) {
    extern __shared__ __align__(16) unsigned char dsm[];
    __nv_bfloat16* at[2] = { (__nv_bfloat16*)dsm,           (__nv_bfloat16*)(dsm + 9216) };
    __nv_bfloat16* xt[2] = { (__nv_bfloat16*)(dsm + 18432), (__nv_bfloat16*)(dsm + 35840) };
    float* ssq_s = (float*)(dsm + 53248);

    const int tid = threadIdx.x, lane = tid & 31, warp = tid >> 5;
    const int b  = blockIdx.y;
    const int d0 = blockIdx.x * 128;
    const int wk = (warp & 3) * 16;     // k-row base for this warp
    const int wd = (warp >> 2) * 64;    // d-col base within tile

    if (tid < 64) ssq_s[tid] = 0.f;

    const size_t rowbase = (size_t)b * NM;

    float acc[8][4];
#pragma unroll
    for (int i = 0; i < 8; i++)
#pragma unroll
        for (int j = 0; j < 4; j++) acc[i][j] = 0.f;

    auto issue = [&](int mc, int s) {
        const size_t mrow = rowbase + mc * 64;
#pragma unroll
        for (int it = 0; it < 2; it++) {     // a tile: 64 m x 64 k
            int idx = tid + it * 256;
            int r = idx >> 3, c = idx & 7;
            cp16(s2u(at[s] + r * 72 + c * 8), g_a + (mrow + r) * NK + c * 8);
        }
#pragma unroll
        for (int it = 0; it < 4; it++) {     // x tile: 64 m x 128 d
            int idx = tid + it * 256;
            int r = idx >> 4, c = idx & 15;
            cp16(s2u(xt[s] + r * 136 + c * 8), g_x16 + (mrow + r) * ND + d0 + c * 8);
        }
        cp_commit();
    };

    issue(0, 0);
    for (int mc = 0; mc < 32; mc++) {
        if (mc + 1 < 32) { issue(mc + 1, (mc + 1) & 1); cp_wait<1>(); }
        else             { cp_wait<0>(); }
        __syncthreads();
        const int s = mc & 1;
#pragma unroll
        for (int ms = 0; ms < 4; ms++) {
            int mb = ms * 16;
            unsigned a0, a1, a2, a3;
            {   // A = a^T (k x m) from [m][k] storage -> ldmatrix.trans
                int i = lane & 7;
                int r = mb + i + ((lane >> 4) & 1) * 8;
                int c = wk + ((lane >> 3) & 1) * 8;
                ldsm_x4t(a0, a1, a2, a3, s2u(at[s] + r * 72 + c));
            }
#pragma unroll
            for (int nt = 0; nt < 8; nt += 2) {
                unsigned b0, b1, b2, b3;
                int r = mb + (lane & 7) + ((lane >> 3) & 1) * 8;
                int c = wd + nt * 8 + ((lane >> 4) & 1) * 8;
                ldsm_x4t(b0, b1, b2, b3, s2u(xt[s] + r * 136 + c));
                mma16816(acc[nt],     a0, a1, a2, a3, b0, b1);
                mma16816(acc[nt + 1], a0, a1, a2, a3, b2, b3);
            }
        }
        __syncthreads();
    }

    // ---- fused epilogue: subtract asum*centroid, write fp32, sumsq partials ----
    const int k0 = wk + (lane >> 2);
    const float as0 = g_asum[b * NK + k0];
    const float as1 = g_asum[b * NK + k0 + 8];
    float* vb = g_vfin + ((size_t)b * NK) * ND;
    float sq0 = 0.f, sq1 = 0.f;
#pragma unroll
    for (int nt = 0; nt < 8; nt++) {
        int dd = d0 + wd + nt * 8 + 2 * (lane & 3);
        float2 c0 = *(const float2*)(cent + (size_t)k0 * ND + dd);
        float2 c1 = *(const float2*)(cent + (size_t)(k0 + 8) * ND + dd);
        float v00 = acc[nt][0] - as0 * c0.x;
        float v01 = acc[nt][1] - as0 * c0.y;
        float v10 = acc[nt][2] - as1 * c1.x;
        float v11 = acc[nt][3] - as1 * c1.y;
        sq0 += v00 * v00 + v01 * v01;
        sq1 += v10 * v10 + v11 * v11;
        *(float2*)(vb + (size_t)k0 * ND + dd)       = make_float2(v00, v01);
        *(float2*)(vb + (size_t)(k0 + 8) * ND + dd) = make_float2(v10, v11);
    }
    // reduce over the 4 lanes sharing a k-row
    sq0 += __shfl_xor_sync(0xffffffffu, sq0, 1);
    sq0 += __shfl_xor_sync(0xffffffffu, sq0, 2);
    sq1 += __shfl_xor_sync(0xffffffffu, sq1, 1);
    sq1 += __shfl_xor_sync(0xffffffffu, sq1, 2);
    if ((lane & 3) == 0) {        // 2 warps (wd halves) contribute per row slot
        atomicAdd(&ssq_s[k0], sq0);
        atomicAdd(&ssq_s[k0 + 8], sq1);
    }
    __syncthreads();
    if (tid < 64)
        g_ssq[(b * NK + tid) * 8 + blockIdx.x] = ssq_s[tid];
}

// ---------------- kernel: per-(b,k) scale = 0.125/||v|| (global norm = 8) ----------------
__global__ __launch_bounds__(256) void k_scale(float* __restrict__ out) {
    const int bk = blockIdx.x;           // b*64 + k
    const int tid = threadIdx.x;
    float tot = 0.f;
#pragma unroll
    for (int j = 0; j < 8; j++) tot += g_ssq[bk * 8 + j];   // fixed order: deterministic
    const float inv = 0.125f / fmaxf(sqrtf(tot), 1e-12f);
    const float4* vr = (const float4*)(g_vfin + (size_t)bk * ND);
    float4* op = (float4*)(out + (size_t)bk * ND);
    float4 v = vr[tid];
    v.x *= inv; v.y *= inv; v.z *= inv; v.w *= inv;
    op[tid] = v;
}

// ---------------- launch ----------------
extern "C" void kernel_launch(void* const* d_in, const int* in_sizes, int n_in,
                              void* d_out, int out_size) {
    const float* x    = (const float*)d_in[0];
    const float* W    = (const float*)d_in[1];
    const float* cent = (const float*)d_in[2];
    float* out = (float*)d_out;

    static int configured = 0;
    if (!configured) {
        cudaFuncSetAttribute(k_nl,   cudaFuncAttributeMaxDynamicSharedMemorySize, NL_SMEM);
        cudaFuncSetAttribute(k_vlad, cudaFuncAttributeMaxDynamicSharedMemorySize, VL_SMEM);
        configured = 1;
    }

    k_wconv<<<256, 256>>>(W);
    k_nl   <<<512, 256, NL_SMEM>>>(x);
    k_vlad <<<dim3(8, 32), 256, VL_SMEM>>>(cent);
    k_scale<<<2048, 256>>>(out);
}

// round 11
// speedup vs baseline: 1.1152x; 1.0046x over previous
#include <cuda_runtime.h>
#include <cuda_bf16.h>
#include <cstdint>

#define NB 32
#define NM 2048
#define ND 1024
#define NK 64
#define BM (NB*NM)   // 65536 rows total

// ---------------- scratch (device globals; no allocs allowed) ----------------
__device__ __nv_bfloat16 g_x16[(size_t)BM * ND];       // 128 MB bf16(x) RAW (not normalized)
__device__ __nv_bfloat16 g_w16[NK * ND];               // W in bf16, k-PERMUTED within 16-groups
__device__ __nv_bfloat16 g_a[(size_t)BM * NK];         // p[m,k] * inv_m  (bf16)
__device__ float         g_asum[NB * NK];              // sum_m p[b,m,k]  (unscaled)
__device__ float         g_ssq[NB * NK * 8];           // per-(b,k) sumsq partials, 8 d-tiles
__device__ int           g_cnt[NB];                    // arrival counters (one per b)

// ---------------- helpers ----------------
static __device__ __forceinline__ unsigned s2u(const void* p) {
    return (unsigned)__cvta_generic_to_shared(p);
}
static __device__ __forceinline__ void cp16(unsigned dst, const void* src) {
    asm volatile("cp.async.cg.shared.global [%0], [%1], 16;\n" :: "r"(dst), "l"(src));
}
static __device__ __forceinline__ void cp_commit() {
    asm volatile("cp.async.commit_group;\n");
}
template<int N> static __device__ __forceinline__ void cp_wait() {
    asm volatile("cp.async.wait_group %0;\n" :: "n"(N));
}
static __device__ __forceinline__ void ldsm_x4(unsigned& r0, unsigned& r1, unsigned& r2, unsigned& r3, unsigned a) {
    asm volatile("ldmatrix.sync.aligned.m8n8.x4.shared.b16 {%0,%1,%2,%3}, [%4];"
                 : "=r"(r0), "=r"(r1), "=r"(r2), "=r"(r3) : "r"(a));
}
static __device__ __forceinline__ void ldsm_x4t(unsigned& r0, unsigned& r1, unsigned& r2, unsigned& r3, unsigned a) {
    asm volatile("ldmatrix.sync.aligned.m8n8.x4.trans.shared.b16 {%0,%1,%2,%3}, [%4];"
                 : "=r"(r0), "=r"(r1), "=r"(r2), "=r"(r3) : "r"(a));
}
static __device__ __forceinline__ void mma16816(float* c,
        unsigned a0, unsigned a1, unsigned a2, unsigned a3, unsigned b0, unsigned b1) {
    asm volatile("mma.sync.aligned.m16n8k16.row.col.f32.bf16.bf16.f32 "
                 "{%0,%1,%2,%3}, {%4,%5,%6,%7}, {%8,%9}, {%0,%1,%2,%3};"
                 : "+f"(c[0]), "+f"(c[1]), "+f"(c[2]), "+f"(c[3])
                 : "r"(a0), "r"(a1), "r"(a2), "r"(a3), "r"(b0), "r"(b1));
}
static __device__ __forceinline__ unsigned packbf(float a, float b) {
    __nv_bfloat162 h;
    h.x = __float2bfloat16_rn(a);
    h.y = __float2bfloat16_rn(b);
    return *reinterpret_cast<unsigned*>(&h);
}

// ---------------- kernel 0: W -> bf16 (k-permuted), zero a_sum + counters ----------------
__global__ __launch_bounds__(256) void k_wconv(const float* __restrict__ W) {
    int i = blockIdx.x * 256 + threadIdx.x;       // grid 256 -> exactly NK*ND
    int kl = i & (ND - 1);
    int j  = kl & 15;
    int sl = 2 * (j >> 2) + (j & 1) + ((j & 2) ? 8 : 0);
    int oc = (kl & ~15) | sl;
    g_w16[(i & ~(ND - 1)) | oc] = __float2bfloat16_rn(W[i]);
    if (i < NB * NK) g_asum[i] = 0.f;
    if (i < NB) g_cnt[i] = 0;
}

// ============ fused: x->bf16 + logits GEMM + row-norm + softmax + a_sum ============
// (R7-proven version, unchanged.) 128 rows per block (grid 512). A-operand
// fragments built directly from x LDG.128 registers; raw bf16 streamed to g_x16.
// W tiles double-buffered via cp.async, consumed with ldsm_x4.
//
// dyn smem layout (bytes):
//   wt[2] [64][72] bf16 @ 0      18432
//   lg    [128][66] f32 @ 18432  33792
//   ssrow [128]     f32 @ 52224    512
//   sas   [64]      f32 @ 52736    256
#define NL_SMEM 52992
__global__ __launch_bounds__(256, 2) void k_nl(const float* __restrict__ x) {
    extern __shared__ __align__(16) unsigned char dsm[];
    __nv_bfloat16* wt[2] = { (__nv_bfloat16*)dsm, (__nv_bfloat16*)(dsm + 9216) };
    float* lg    = (float*)(dsm + 18432);
    float* ssrow = (float*)(dsm + 52224);
    float* sas   = (float*)(dsm + 52736);

    const int tid = threadIdx.x, lane = tid & 31, warp = tid >> 5;
    const int m0 = blockIdx.x * 128;
    const int b  = m0 >> 11;

    if (tid < 64) sas[tid] = 0.f;

    const int gr = lane >> 2, q = lane & 3;
    const int ar = warp * 16;                       // warp's 16 m-rows
    const size_t row0 = (size_t)(m0 + ar + gr);     // lo row; hi row = row0 + 8

    float4 xr[2][4][2];
    float ss0 = 0.f, ss1 = 0.f;

    float acc[8][4];
#pragma unroll
    for (int i = 0; i < 8; i++)
#pragma unroll
        for (int j = 0; j < 4; j++) acc[i][j] = 0.f;

    auto ldw = [&](int ch, int s) {
#pragma unroll
        for (int it = 0; it < 2; it++) {
            int idx = tid + it * 256;
            int r = idx >> 3, c = idx & 7;
            cp16(s2u(wt[s] + r * 72 + c * 8), g_w16 + (size_t)r * ND + ch * 64 + c * 8);
        }
        cp_commit();
    };

    const float* xb = x + row0 * ND + q * 4;

    // ---- prologue ----
#pragma unroll
    for (int ds = 0; ds < 4; ds++) {
        xr[0][ds][0] = *(const float4*)(xb + ds * 16);
        xr[0][ds][1] = *(const float4*)(xb + ds * 16 + 8 * ND);
    }
    ldw(0, 0);
    ldw(1, 1);
#pragma unroll
    for (int ds = 0; ds < 4; ds++) {
        xr[1][ds][0] = *(const float4*)(xb + 64 + ds * 16);
        xr[1][ds][1] = *(const float4*)(xb + 64 + ds * 16 + 8 * ND);
    }
    cp_wait<1>();
    __syncthreads();

    // ---- main loop: ch unrolled by 2 so buffer indices are literals ----
    auto body = [&](int ch, int cb) {
#pragma unroll
        for (int ds = 0; ds < 4; ds++) {
            float4 f0 = xr[cb][ds][0];
            float4 f1 = xr[cb][ds][1];
            ss0 += f0.x * f0.x + f0.y * f0.y + f0.z * f0.z + f0.w * f0.w;
            ss1 += f1.x * f1.x + f1.y * f1.y + f1.z * f1.z + f1.w * f1.w;
            unsigned a0 = packbf(f0.x, f0.y), a2 = packbf(f0.z, f0.w);
            unsigned a1 = packbf(f1.x, f1.y), a3 = packbf(f1.z, f1.w);
            {   // raw bf16 out (natural order) for k_vlad
                __nv_bfloat16* gx = g_x16 + row0 * ND + ch * 64 + ds * 16 + q * 4;
                uint2 u0; u0.x = a0; u0.y = a2;
                uint2 u1; u1.x = a1; u1.y = a3;
                *(uint2*)gx            = u0;
                *(uint2*)(gx + 8 * ND) = u1;
            }
#pragma unroll
            for (int nt = 0; nt < 8; nt += 2) {
                unsigned b0, b1, b2, b3;
                int r = nt * 8 + (lane & 7) + ((lane >> 4) & 1) * 8;
                int c = ds * 16 + ((lane >> 3) & 1) * 8;
                ldsm_x4(b0, b1, b2, b3, s2u(wt[cb] + r * 72 + c));
                mma16816(acc[nt],     a0, a1, a2, a3, b0, b1);
                mma16816(acc[nt + 1], a0, a1, a2, a3, b2, b3);
            }
        }
        if (ch + 2 < 16) {
#pragma unroll
            for (int ds = 0; ds < 4; ds++) {
                xr[cb][ds][0] = *(const float4*)(xb + (ch + 2) * 64 + ds * 16);
                xr[cb][ds][1] = *(const float4*)(xb + (ch + 2) * 64 + ds * 16 + 8 * ND);
            }
        }
        __syncthreads();                 // all reads of wt[cb] complete
        if (ch + 2 < 16) { ldw(ch + 2, cb); cp_wait<1>(); }
        else             cp_wait<0>();
        __syncthreads();                 // wt writes visible
    };
    for (int ch2 = 0; ch2 < 16; ch2 += 2) {
        body(ch2,     0);
        body(ch2 + 1, 1);
    }

    // ---- row sum-of-squares: reduce over the 4 q-lanes ----
    ss0 += __shfl_xor_sync(0xffffffffu, ss0, 1);
    ss0 += __shfl_xor_sync(0xffffffffu, ss0, 2);
    ss1 += __shfl_xor_sync(0xffffffffu, ss1, 1);
    ss1 += __shfl_xor_sync(0xffffffffu, ss1, 2);
    if (q == 0) {
        ssrow[ar + gr]     = ss0;
        ssrow[ar + gr + 8] = ss1;
    }
    // ---- dump logits ----
#pragma unroll
    for (int nt = 0; nt < 8; nt++) {
        int r0 = ar + (lane >> 2);
        int c0 = nt * 8 + 2 * (lane & 3);
        lg[r0 * 66 + c0]           = acc[nt][0];
        lg[r0 * 66 + c0 + 1]       = acc[nt][1];
        lg[(r0 + 8) * 66 + c0]     = acc[nt][2];
        lg[(r0 + 8) * 66 + c0 + 1] = acc[nt][3];
    }
    __syncthreads();

    // ---- softmax: each warp does its 16 rows; lane owns cols (2l, 2l+1) ----
    float s0 = 0.f, s1 = 0.f;
    const int c0 = 2 * lane, c1 = 2 * lane + 1;
#pragma unroll 1
    for (int r = 0; r < 16; r++) {
        int rr = ar + r;
        float inv = 1.0f / fmaxf(sqrtf(ssrow[rr]), 1e-12f);
        float v0 = lg[rr * 66 + c0] * inv, v1 = lg[rr * 66 + c1] * inv;
        float mx = fmaxf(v0, v1);
#pragma unroll
        for (int o = 16; o > 0; o >>= 1) mx = fmaxf(mx, __shfl_xor_sync(0xffffffffu, mx, o));
        float e0 = expf(v0 - mx), e1 = expf(v1 - mx);
        float sm = e0 + e1;
#pragma unroll
        for (int o = 16; o > 0; o >>= 1) sm += __shfl_xor_sync(0xffffffffu, sm, o);
        float is = 1.0f / sm;
        float p0 = e0 * is, p1 = e1 * is;
        s0 += p0; s1 += p1;
        __nv_bfloat162 h;                    // store p * inv_m  (normalization folded in)
        h.x = __float2bfloat16_rn(p0 * inv);
        h.y = __float2bfloat16_rn(p1 * inv);
        ((__nv_bfloat162*)(g_a + (size_t)(m0 + rr) * NK))[lane] = h;
    }
    atomicAdd(&sas[c0], s0);
    atomicAdd(&sas[c1], s1);
    __syncthreads();
    if (tid < 64) atomicAdd(&g_asum[b * NK + tid], sas[tid]);
}

// ============ kernel: vlad + centroid-subtract + GLOBAL norm + final write ============
// grid (8 d-tiles of 128, 32 b) = 256 CTAs, 2/SM -> 296 slots: guaranteed single
// co-resident wave, so the cross-CTA spin below cannot deadlock. Full M=2048 per
// CTA (32 chunks), 2-stage cp.async double buffering (R8/R10-proven mainloop).
// Epilogue: v = acc - asum*cent kept IN REGISTERS; CTA deposits its sumsq partial,
// then spins until all 8 d-CTAs of its b arrive; reads partials in fixed order
// (deterministic), scales regs by 0.125/||v||, writes `out` directly.
// No g_vfin round-trip, no k_scale launch.
//
// dyn smem: at[2] 9216 ea @0 | xt[2] 17408 ea @18432 | ssq_s[64] f32 @53248
#define VL_SMEM 53504
__global__ __launch_bounds__(256, 2) void k_vlad(const float* __restrict__ cent,
                                                 float* __restrict__ out) {
    extern __shared__ __align__(16) unsigned char dsm[];
    __nv_bfloat16* at[2] = { (__nv_bfloat16*)dsm,           (__nv_bfloat16*)(dsm + 9216) };
    __nv_bfloat16* xt[2] = { (__nv_bfloat16*)(dsm + 18432), (__nv_bfloat16*)(dsm + 35840) };
    float* ssq_s = (float*)(dsm + 53248);

    const int tid = threadIdx.x, lane = tid & 31, warp = tid >> 5;
    const int b  = blockIdx.y;
    const int d0 = blockIdx.x * 128;
    const int wk = (warp & 3) * 16;     // k-row base for this warp
    const int wd = (warp >> 2) * 64;    // d-col base within tile

    if (tid < 64) ssq_s[tid] = 0.f;

    const size_t rowbase = (size_t)b * NM;

    float acc[8][4];
#pragma unroll
    for (int i = 0; i < 8; i++)
#pragma unroll
        for (int j = 0; j < 4; j++) acc[i][j] = 0.f;

    auto issue = [&](int mc, int s) {
        const size_t mrow = rowbase + mc * 64;
#pragma unroll
        for (int it = 0; it < 2; it++) {     // a tile: 64 m x 64 k
            int idx = tid + it * 256;
            int r = idx >> 3, c = idx & 7;
            cp16(s2u(at[s] + r * 72 + c * 8), g_a + (mrow + r) * NK + c * 8);
        }
#pragma unroll
        for (int it = 0; it < 4; it++) {     // x tile: 64 m x 128 d
            int idx = tid + it * 256;
            int r = idx >> 4, c = idx & 15;
            cp16(s2u(xt[s] + r * 136 + c * 8), g_x16 + (mrow + r) * ND + d0 + c * 8);
        }
        cp_commit();
    };

    issue(0, 0);
    for (int mc = 0; mc < 32; mc++) {
        if (mc + 1 < 32) { issue(mc + 1, (mc + 1) & 1); cp_wait<1>(); }
        else             { cp_wait<0>(); }
        __syncthreads();
        const int s = mc & 1;
#pragma unroll
        for (int ms = 0; ms < 4; ms++) {
            int mb = ms * 16;
            unsigned a0, a1, a2, a3;
            {   // A = a^T (k x m) from [m][k] storage -> ldmatrix.trans
                int i = lane & 7;
                int r = mb + i + ((lane >> 4) & 1) * 8;
                int c = wk + ((lane >> 3) & 1) * 8;
                ldsm_x4t(a0, a1, a2, a3, s2u(at[s] + r * 72 + c));
            }
#pragma unroll
            for (int nt = 0; nt < 8; nt += 2) {
                unsigned b0, b1, b2, b3;
                int r = mb + (lane & 7) + ((lane >> 3) & 1) * 8;
                int c = wd + nt * 8 + ((lane >> 4) & 1) * 8;
                ldsm_x4t(b0, b1, b2, b3, s2u(xt[s] + r * 136 + c));
                mma16816(acc[nt],     a0, a1, a2, a3, b0, b1);
                mma16816(acc[nt + 1], a0, a1, a2, a3, b2, b3);
            }
        }
        __syncthreads();
    }

    // ---- epilogue part 1: v = acc - asum*cent (kept in regs), sumsq partials ----
    const int k0 = wk + (lane >> 2);
    const float as0 = g_asum[b * NK + k0];
    const float as1 = g_asum[b * NK + k0 + 8];
    float sq0 = 0.f, sq1 = 0.f;
#pragma unroll
    for (int nt = 0; nt < 8; nt++) {
        int dd = d0 + wd + nt * 8 + 2 * (lane & 3);
        float2 c0 = *(const float2*)(cent + (size_t)k0 * ND + dd);
        float2 c1 = *(const float2*)(cent + (size_t)(k0 + 8) * ND + dd);
        acc[nt][0] -= as0 * c0.x;
        acc[nt][1] -= as0 * c0.y;
        acc[nt][2] -= as1 * c1.x;
        acc[nt][3] -= as1 * c1.y;
        sq0 += acc[nt][0] * acc[nt][0] + acc[nt][1] * acc[nt][1];
        sq1 += acc[nt][2] * acc[nt][2] + acc[nt][3] * acc[nt][3];
    }
    // reduce over the 4 lanes sharing a k-row
    sq0 += __shfl_xor_sync(0xffffffffu, sq0, 1);
    sq0 += __shfl_xor_sync(0xffffffffu, sq0, 2);
    sq1 += __shfl_xor_sync(0xffffffffu, sq1, 1);
    sq1 += __shfl_xor_sync(0xffffffffu, sq1, 2);
    if ((lane & 3) == 0) {        // 2 warps (wd halves) contribute per row slot
        atomicAdd(&ssq_s[k0], sq0);
        atomicAdd(&ssq_s[k0 + 8], sq1);
    }
    __syncthreads();
    if (tid < 64)
        g_ssq[(b * NK + tid) * 8 + blockIdx.x] = ssq_s[tid];
    __threadfence();              // make this CTA's partial globally visible
    __syncthreads();

    // ---- epilogue part 2: arrive + spin until all 8 d-CTAs of this b done ----
    if (tid == 0) {
        atomicAdd(&g_cnt[b], 1);
        int v;
        do {
            asm volatile("ld.global.acquire.gpu.s32 %0, [%1];" : "=r"(v) : "l"(g_cnt + b));
        } while (v < 8);
    }
    __syncthreads();

    // ---- epilogue part 3: global tot (fixed order), scale regs, write out ----
    float tot0 = 0.f, tot1 = 0.f;
#pragma unroll
    for (int j = 0; j < 8; j++) {
        tot0 += __ldcg(g_ssq + (b * NK + k0) * 8 + j);
        tot1 += __ldcg(g_ssq + (b * NK + k0 + 8) * 8 + j);
    }
    const float inv0 = 0.125f / fmaxf(sqrtf(tot0), 1e-12f);   // global norm = 8 exactly
    const float inv1 = 0.125f / fmaxf(sqrtf(tot1), 1e-12f);
    float* ob = out + ((size_t)b * NK) * ND;
#pragma unroll
    for (int nt = 0; nt < 8; nt++) {
        int dd = d0 + wd + nt * 8 + 2 * (lane & 3);
        *(float2*)(ob + (size_t)k0 * ND + dd) =
            make_float2(acc[nt][0] * inv0, acc[nt][1] * inv0);
        *(float2*)(ob + (size_t)(k0 + 8) * ND + dd) =
            make_float2(acc[nt][2] * inv1, acc[nt][3] * inv1);
    }
}

// ---------------- launch ----------------
extern "C" void kernel_launch(void* const* d_in, const int* in_sizes, int n_in,
                              void* d_out, int out_size) {
    const float* x    = (const float*)d_in[0];
    const float* W    = (const float*)d_in[1];
    const float* cent = (const float*)d_in[2];
    float* out = (float*)d_out;

    static int configured = 0;
    if (!configured) {
        cudaFuncSetAttribute(k_nl,   cudaFuncAttributeMaxDynamicSharedMemorySize, NL_SMEM);
        cudaFuncSetAttribute(k_vlad, cudaFuncAttributeMaxDynamicSharedMemorySize, VL_SMEM);
        configured = 1;
    }

    k_wconv<<<256, 256>>>(W);
    k_nl   <<<512, 256, NL_SMEM>>>(x);
    k_vlad <<<dim3(8, 32), 256, VL_SMEM>>>(cent, out);
}